// round 7
// baseline (speedup 1.0000x reference)
#include <cuda_runtime.h>
#include <cuda_bf16.h>
#include <cstdint>
#include <math.h>

// Problem constants
#define BB   4
#define SS   2048
#define EE   1024
#define HHN  16
#define DKH  64
#define FFD  4096
#define MR   (BB*SS)   /* 8192 rows */

typedef __nv_bfloat16 bf16;

// ---------------------------------------------------------------------------
// Scratch (static __device__ arrays)
// ---------------------------------------------------------------------------
__device__ float g_qkv[(size_t)MR * 3 * EE];   // 96 MB (fp32, attention input)
__device__ float g_r1 [(size_t)MR * EE];       // 32 MB
__device__ float g_x1 [(size_t)MR * EE];       // 32 MB (fp32 for FFN2 residual)
__device__ float g_r2 [(size_t)MR * EE];       // 32 MB

__device__ bf16 g_x_h  [(size_t)MR * EE];
__device__ bf16 g_x_l  [(size_t)MR * EE];
__device__ bf16 g_att_h[(size_t)MR * EE];
__device__ bf16 g_att_l[(size_t)MR * EE];
__device__ bf16 g_x1_h [(size_t)MR * EE];
__device__ bf16 g_x1_l [(size_t)MR * EE];
__device__ bf16 g_h_h  [(size_t)MR * FFD];
__device__ bf16 g_h_l  [(size_t)MR * FFD];

__device__ bf16 g_wqkv_h[(size_t)3 * EE * EE];
__device__ bf16 g_wqkv_l[(size_t)3 * EE * EE];
__device__ bf16 g_wout_h[(size_t)EE * EE];
__device__ bf16 g_wout_l[(size_t)EE * EE];
__device__ bf16 g_w1_h  [(size_t)FFD * EE];
__device__ bf16 g_w1_l  [(size_t)FFD * EE];
__device__ bf16 g_w2_h  [(size_t)EE * FFD];
__device__ bf16 g_w2_l  [(size_t)EE * FFD];

// ---------------------------------------------------------------------------
// Helpers
// ---------------------------------------------------------------------------
__device__ __forceinline__ uint32_t smem_u32(const void* p) {
    uint32_t a;
    asm("{ .reg .u64 t; cvta.to.shared.u64 t, %1; cvt.u32.u64 %0, t; }"
        : "=r"(a) : "l"(p));
    return a;
}

__device__ __forceinline__ void mma16816(float* c, const uint32_t* a, const uint32_t* b) {
    asm volatile(
        "mma.sync.aligned.m16n8k16.row.col.f32.bf16.bf16.f32 "
        "{%0,%1,%2,%3}, {%4,%5,%6,%7}, {%8,%9}, {%0,%1,%2,%3};"
        : "+f"(c[0]), "+f"(c[1]), "+f"(c[2]), "+f"(c[3])
        : "r"(a[0]), "r"(a[1]), "r"(a[2]), "r"(a[3]), "r"(b[0]), "r"(b[1]));
}

__device__ __forceinline__ void ldsm4(uint32_t* r, uint32_t addr) {
    asm volatile("ldmatrix.sync.aligned.m8n8.x4.shared.b16 {%0,%1,%2,%3}, [%4];"
        : "=r"(r[0]), "=r"(r[1]), "=r"(r[2]), "=r"(r[3]) : "r"(addr));
}

__device__ __forceinline__ void ldsm4t(uint32_t* r, uint32_t addr) {
    asm volatile("ldmatrix.sync.aligned.m8n8.x4.trans.shared.b16 {%0,%1,%2,%3}, [%4];"
        : "=r"(r[0]), "=r"(r[1]), "=r"(r[2]), "=r"(r[3]) : "r"(addr));
}

__device__ __forceinline__ void cp16(uint32_t saddr, const void* g) {
    asm volatile("cp.async.cg.shared.global [%0], [%1], 16;" :: "r"(saddr), "l"(g) : "memory");
}
#define CP_COMMIT() asm volatile("cp.async.commit_group;" ::: "memory")

// split pair of floats into hi/lo bf16x2 words
__device__ __forceinline__ void split2(float a, float b, uint32_t& hh, uint32_t& ll) {
    asm("cvt.rn.bf16x2.f32 %0,%1,%2;" : "=r"(hh) : "f"(b), "f"(a));
    float ra = a - __uint_as_float(hh << 16);
    float rb = b - __uint_as_float(hh & 0xFFFF0000u);
    asm("cvt.rn.bf16x2.f32 %0,%1,%2;" : "=r"(ll) : "f"(rb), "f"(ra));
}

__device__ __forceinline__ void cvt_store8(char* hi, char* lo, uint32_t boff, float4 v) {
    uint32_t h0, h1, l0, l1;
    split2(v.x, v.y, h0, l0);
    split2(v.z, v.w, h1, l1);
    *(uint2*)(hi + boff) = make_uint2(h0, h1);
    *(uint2*)(lo + boff) = make_uint2(l0, l1);
}

// ---------------------------------------------------------------------------
// fp32 -> bf16 hi/lo split kernel (elementwise, float4 per thread)
// ---------------------------------------------------------------------------
__global__ __launch_bounds__(256)
void split_kernel(const float* __restrict__ s, bf16* __restrict__ h,
                  bf16* __restrict__ l, int n4)
{
    int i = blockIdx.x * 256 + threadIdx.x;
    if (i >= n4) return;
    float4 v = ((const float4*)s)[i];
    uint32_t h0, h1, l0, l1;
    split2(v.x, v.y, h0, l0);
    split2(v.z, v.w, h1, l1);
    ((uint2*)h)[i] = make_uint2(h0, h1);
    ((uint2*)l)[i] = make_uint2(l0, l1);
}

// ---------------------------------------------------------------------------
// GEMM on pre-split bf16 hi/lo inputs: C = A @ W^T (+bias, +res, relu)
// 3-pass split accumulate. CTA 128x128, BK=32, 256 thr, 2 CTAs/SM, cp.async.
// ---------------------------------------------------------------------------
#define SBYTE 80
#define TO_AH 0
#define TO_AL 10240
#define TO_BH 20480
#define TO_BL 30720
#define STAGE 40960
#define GSM_TOTAL (2 * STAGE)

template<bool RELU, bool RES, bool OUTBF>
__global__ __launch_bounds__(256, 2)
void gemm_bf(const bf16* __restrict__ Ah, const bf16* __restrict__ Al,
             const bf16* __restrict__ Bh, const bf16* __restrict__ Bl,
             const float* __restrict__ bias, const float* __restrict__ res,
             float* __restrict__ C, bf16* __restrict__ Ch, bf16* __restrict__ Cl,
             int N, int K)
{
    extern __shared__ char sm[];
    const int tid = threadIdx.x, lane = tid & 31, wid = tid >> 5;
    const int wm = wid & 1;
    const int wn = wid >> 1;
    const int bm = blockIdx.y * 128, bn = blockIdx.x * 128;
    const uint32_t sbase = smem_u32(sm);

    const uint32_t a_off = (uint32_t)(wm * 64 + (lane & 15)) * SBYTE + ((lane >> 4) * 16);
    const uint32_t b_off = (uint32_t)(wn * 32 + (lane & 7) + ((lane >> 4) << 3)) * SBYTE
                         + (((lane >> 3) & 1) * 16);

    const bf16* Abh = Ah + (size_t)bm * K;
    const bf16* Abl = Al + (size_t)bm * K;
    const bf16* Bbh = Bh + (size_t)bn * K;
    const bf16* Bbl = Bl + (size_t)bn * K;

    auto load_stage = [&](int buf, int kt) {
        const uint32_t s2 = sbase + buf * STAGE;
#pragma unroll
        for (int i = 0; i < 2; i++) {
            int ch  = tid + 256 * i;
            int row = ch >> 2, c = ch & 3;
            uint32_t so = (uint32_t)row * SBYTE + c * 16;
            size_t   go = (size_t)row * K + (size_t)kt * 32 + c * 8;
            cp16(s2 + TO_AH + so, Abh + go);
            cp16(s2 + TO_AL + so, Abl + go);
            cp16(s2 + TO_BH + so, Bbh + go);
            cp16(s2 + TO_BL + so, Bbl + go);
        }
        CP_COMMIT();
    };

    float acc[4][4][4];
#pragma unroll
    for (int mt = 0; mt < 4; mt++)
#pragma unroll
        for (int nt = 0; nt < 4; nt++)
#pragma unroll
            for (int j = 0; j < 4; j++) acc[mt][nt][j] = 0.f;

    load_stage(0, 0);
    load_stage(1, 1);

    const int KT = K >> 5;
    for (int kt = 0; kt < KT; kt++) {
        if (kt + 1 < KT) { asm volatile("cp.async.wait_group 1;" ::: "memory"); }
        else             { asm volatile("cp.async.wait_group 0;" ::: "memory"); }
        __syncthreads();

        const uint32_t base = sbase + (kt & 1) * STAGE;
#pragma unroll
        for (int ks = 0; ks < 2; ks++) {
            uint32_t ah[4][4], al[4][4], bh[2][4], bl[2][4];
#pragma unroll
            for (int t = 0; t < 4; t++) {
                ldsm4(ah[t], base + TO_AH + a_off + t * (16 * SBYTE) + ks * 32);
                ldsm4(al[t], base + TO_AL + a_off + t * (16 * SBYTE) + ks * 32);
            }
#pragma unroll
            for (int i = 0; i < 2; i++) {
                ldsm4(bh[i], base + TO_BH + b_off + i * (16 * SBYTE) + ks * 32);
                ldsm4(bl[i], base + TO_BL + b_off + i * (16 * SBYTE) + ks * 32);
            }
#pragma unroll
            for (int mt = 0; mt < 4; mt++)
#pragma unroll
                for (int nt = 0; nt < 4; nt++) {
                    const uint32_t* bph = &bh[nt >> 1][(nt & 1) * 2];
                    const uint32_t* bpl = &bl[nt >> 1][(nt & 1) * 2];
                    mma16816(acc[mt][nt], al[mt], bph);
                    mma16816(acc[mt][nt], ah[mt], bpl);
                    mma16816(acc[mt][nt], ah[mt], bph);
                }
        }
        __syncthreads();
        if (kt + 2 < KT) load_stage(kt & 1, kt + 2);
    }

    // Epilogue
    const int erow = bm + wm * 64 + (lane >> 2);
    const int ecol = bn + wn * 32 + (lane & 3) * 2;
#pragma unroll
    for (int mt = 0; mt < 4; mt++)
#pragma unroll
        for (int nt = 0; nt < 4; nt++) {
            const int col = ecol + nt * 8;
            float2 bv = *(const float2*)(bias + col);
#pragma unroll
            for (int h2 = 0; h2 < 2; h2++) {
                const int row = erow + mt * 16 + h2 * 8;
                float o0 = acc[mt][nt][h2 * 2 + 0] + bv.x;
                float o1 = acc[mt][nt][h2 * 2 + 1] + bv.y;
                if (RES) {
                    float2 rv = *(const float2*)(res + (size_t)row * N + col);
                    o0 += rv.x; o1 += rv.y;
                }
                if (RELU) { o0 = fmaxf(o0, 0.f); o1 = fmaxf(o1, 0.f); }
                if (OUTBF) {
                    uint32_t hh, ll;
                    split2(o0, o1, hh, ll);
                    *(uint32_t*)(Ch + (size_t)row * N + col) = hh;
                    *(uint32_t*)(Cl + (size_t)row * N + col) = ll;
                } else {
                    *(float2*)(C + (size_t)row * N + col) = make_float2(o0, o1);
                }
            }
        }
}

// ---------------------------------------------------------------------------
// Flash attention via mma.sync (bf16 3-pass split) — epilogue emits bf16 hi/lo
// ---------------------------------------------------------------------------
#define ASTR   144
#define AQ_HI  0
#define AQ_LO  (128 * ASTR)
#define AK_HI  (2 * 128 * ASTR)
#define AK_LO  (AK_HI + 64 * ASTR)
#define AV_HI  (AK_LO + 64 * ASTR)
#define AV_LO  (AV_HI + 64 * ASTR)
#define ATT_SMEM (AV_LO + 64 * ASTR)   /* 73728 */

__global__ __launch_bounds__(256, 1)
void attn_mma(const float* __restrict__ qkv,
              bf16* __restrict__ out_h, bf16* __restrict__ out_l)
{
    extern __shared__ char sm[];
    const uint32_t sb = smem_u32(sm);
    const int tid = threadIdx.x, lane = tid & 31, w = tid >> 5;
    const int qt = blockIdx.x;
    const int bh = blockIdx.y;
    const int b = bh >> 4, h = bh & 15;

    const float* base = qkv + (size_t)b * SS * (3 * EE);

    {
        const int c4q = tid & 15, r0q = tid >> 4;
#pragma unroll
        for (int i = 0; i < 8; i++) {
            int r = r0q + 16 * i;
            float4 v = *(const float4*)(base + (size_t)(qt * 128 + r) * (3 * EE) + h * 64 + c4q * 4);
            v.x *= 0.125f; v.y *= 0.125f; v.z *= 0.125f; v.w *= 0.125f;
            cvt_store8(sm + AQ_HI, sm + AQ_LO, (uint32_t)r * ASTR + c4q * 8, v);
        }
    }

    const int c4 = tid & 15, kr0 = tid >> 4;
    const float* kbase = qkv + (size_t)b * SS * (3 * EE) + EE + h * 64 + c4 * 4;
    const float* vbase = kbase + EE;

    float4 kreg[4], vreg[4];
#pragma unroll
    for (int i = 0; i < 4; i++) {
        kreg[i] = *(const float4*)(kbase + (size_t)(kr0 + 16 * i) * (3 * EE));
        vreg[i] = *(const float4*)(vbase + (size_t)(kr0 + 16 * i) * (3 * EE));
    }
#pragma unroll
    for (int i = 0; i < 4; i++) {
        uint32_t o = (uint32_t)(kr0 + 16 * i) * ASTR + c4 * 8;
        cvt_store8(sm + AK_HI, sm + AK_LO, o, kreg[i]);
        cvt_store8(sm + AV_HI, sm + AV_LO, o, vreg[i]);
    }
    __syncthreads();

    const uint32_t a_off = (uint32_t)(w * 16 + (lane & 15)) * ASTR + ((lane >> 4) * 16);
    const uint32_t b_off = (uint32_t)((lane & 7) + ((lane >> 4) << 3)) * ASTR
                         + (((lane >> 3) & 1) * 16);
    const uint32_t v_off = (uint32_t)(lane & 15) * ASTR + ((lane >> 4) * 16);

    float mA = -1e30f, mB = -1e30f, lA = 0.f, lB = 0.f;
    float O[8][4];
#pragma unroll
    for (int j = 0; j < 8; j++)
#pragma unroll
        for (int k = 0; k < 4; k++) O[j][k] = 0.f;

    const int NT = SS / 64;
    for (int kt = 0; kt < NT; kt++) {
        const bool more = (kt + 1 < NT);
        if (more) {
#pragma unroll
            for (int i = 0; i < 4; i++) {
                kreg[i] = *(const float4*)(kbase + (size_t)((kt + 1) * 64 + kr0 + 16 * i) * (3 * EE));
                vreg[i] = *(const float4*)(vbase + (size_t)((kt + 1) * 64 + kr0 + 16 * i) * (3 * EE));
            }
        }

        float S[8][4];
#pragma unroll
        for (int j = 0; j < 8; j++)
#pragma unroll
            for (int k = 0; k < 4; k++) S[j][k] = 0.f;

#pragma unroll
        for (int kd = 0; kd < 4; kd++) {
            uint32_t ah[4], al[4];
            ldsm4(ah, sb + AQ_HI + a_off + kd * 32);
            ldsm4(al, sb + AQ_LO + a_off + kd * 32);
#pragma unroll
            for (int i = 0; i < 4; i++) {
                uint32_t bh4[4], bl4[4];
                ldsm4(bh4, sb + AK_HI + b_off + i * (16 * ASTR) + kd * 32);
                ldsm4(bl4, sb + AK_LO + b_off + i * (16 * ASTR) + kd * 32);
                mma16816(S[2 * i],     al, &bh4[0]);
                mma16816(S[2 * i],     ah, &bl4[0]);
                mma16816(S[2 * i],     ah, &bh4[0]);
                mma16816(S[2 * i + 1], al, &bh4[2]);
                mma16816(S[2 * i + 1], ah, &bl4[2]);
                mma16816(S[2 * i + 1], ah, &bh4[2]);
            }
        }

        float txA = -1e30f, txB = -1e30f;
#pragma unroll
        for (int j = 0; j < 8; j++) {
            txA = fmaxf(txA, fmaxf(S[j][0], S[j][1]));
            txB = fmaxf(txB, fmaxf(S[j][2], S[j][3]));
        }
        txA = fmaxf(txA, __shfl_xor_sync(0xffffffffu, txA, 1));
        txA = fmaxf(txA, __shfl_xor_sync(0xffffffffu, txA, 2));
        txB = fmaxf(txB, __shfl_xor_sync(0xffffffffu, txB, 1));
        txB = fmaxf(txB, __shfl_xor_sync(0xffffffffu, txB, 2));
        const float mnA = fmaxf(mA, txA), mnB = fmaxf(mB, txB);
        const float cA = __expf(mA - mnA), cB = __expf(mB - mnB);

        float sA = 0.f, sB = 0.f;
#pragma unroll
        for (int j = 0; j < 8; j++) {
            S[j][0] = __expf(S[j][0] - mnA);
            S[j][1] = __expf(S[j][1] - mnA);
            S[j][2] = __expf(S[j][2] - mnB);
            S[j][3] = __expf(S[j][3] - mnB);
            sA += S[j][0] + S[j][1];
            sB += S[j][2] + S[j][3];
        }
        sA += __shfl_xor_sync(0xffffffffu, sA, 1);
        sA += __shfl_xor_sync(0xffffffffu, sA, 2);
        sB += __shfl_xor_sync(0xffffffffu, sB, 1);
        sB += __shfl_xor_sync(0xffffffffu, sB, 2);
        lA = lA * cA + sA;  mA = mnA;
        lB = lB * cB + sB;  mB = mnB;
#pragma unroll
        for (int j = 0; j < 8; j++) {
            O[j][0] *= cA; O[j][1] *= cA;
            O[j][2] *= cB; O[j][3] *= cB;
        }

#pragma unroll
        for (int kk = 0; kk < 4; kk++) {
            uint32_t ph[4], pl[4];
#pragma unroll
            for (int u = 0; u < 2; u++) {
                const float* sp = S[2 * kk + u];
#pragma unroll
                for (int hf = 0; hf < 2; hf++) {
                    uint32_t hh, ll;
                    split2(sp[2 * hf], sp[2 * hf + 1], hh, ll);
                    ph[2 * u + hf] = hh;
                    pl[2 * u + hf] = ll;
                }
            }
#pragma unroll
            for (int dimc = 0; dimc < 4; dimc++) {
                uint32_t vh[4], vl[4];
                ldsm4t(vh, sb + AV_HI + v_off + (uint32_t)(kk * 16) * ASTR + dimc * 32);
                ldsm4t(vl, sb + AV_LO + v_off + (uint32_t)(kk * 16) * ASTR + dimc * 32);
                mma16816(O[2 * dimc],     pl, &vh[0]);
                mma16816(O[2 * dimc],     ph, &vl[0]);
                mma16816(O[2 * dimc],     ph, &vh[0]);
                mma16816(O[2 * dimc + 1], pl, &vh[2]);
                mma16816(O[2 * dimc + 1], ph, &vl[2]);
                mma16816(O[2 * dimc + 1], ph, &vh[2]);
            }
        }

        __syncthreads();
        if (more) {
#pragma unroll
            for (int i = 0; i < 4; i++) {
                uint32_t o = (uint32_t)(kr0 + 16 * i) * ASTR + c4 * 8;
                cvt_store8(sm + AK_HI, sm + AK_LO, o, kreg[i]);
                cvt_store8(sm + AV_HI, sm + AV_LO, o, vreg[i]);
            }
            __syncthreads();
        }
    }

    // epilogue -> bf16 hi/lo
    const float invA = 1.f / lA, invB = 1.f / lB;
    const size_t rowA = (size_t)b * SS + qt * 128 + w * 16 + (lane >> 2);
    const size_t idxA = rowA * EE + h * 64 + (lane & 3) * 2;
#pragma unroll
    for (int j = 0; j < 8; j++) {
        uint32_t hh, ll;
        split2(O[j][0] * invA, O[j][1] * invA, hh, ll);
        *(uint32_t*)(out_h + idxA + j * 8) = hh;
        *(uint32_t*)(out_l + idxA + j * 8) = ll;
        split2(O[j][2] * invB, O[j][3] * invB, hh, ll);
        *(uint32_t*)(out_h + idxA + (size_t)8 * EE + j * 8) = hh;
        *(uint32_t*)(out_l + idxA + (size_t)8 * EE + j * 8) = ll;
    }
}

// ---------------------------------------------------------------------------
// LayerNorm — optionally emits bf16 hi/lo alongside fp32
// ---------------------------------------------------------------------------
template<bool EMIT>
__global__ __launch_bounds__(256)
void ln_kernel(const float* __restrict__ r, const float* __restrict__ g,
               const float* __restrict__ be, float* __restrict__ out,
               bf16* __restrict__ oh, bf16* __restrict__ ol)
{
    const int row = blockIdx.x;
    const int tid = threadIdx.x;
    const int lane = tid & 31, warp = tid >> 5;

    float4 v = ((const float4*)(r + (size_t)row * EE))[tid];
    float s  = v.x + v.y + v.z + v.w;
    float sq = v.x * v.x + v.y * v.y + v.z * v.z + v.w * v.w;
#pragma unroll
    for (int o = 16; o; o >>= 1) {
        s  += __shfl_xor_sync(0xffffffffu, s,  o);
        sq += __shfl_xor_sync(0xffffffffu, sq, o);
    }
    __shared__ float ss[8], ssq[8];
    if (lane == 0) { ss[warp] = s; ssq[warp] = sq; }
    __syncthreads();
    float ts = 0.f, tq = 0.f;
#pragma unroll
    for (int i = 0; i < 8; i++) { ts += ss[i]; tq += ssq[i]; }
    float mu   = ts * (1.0f / EE);
    float var  = tq * (1.0f / EE) - mu * mu;
    float rstd = rsqrtf(var + 1e-5f);

    float4 gv = ((const float4*)g)[tid];
    float4 bv = ((const float4*)be)[tid];
    float4 o;
    o.x = (v.x - mu) * rstd * gv.x + bv.x;
    o.y = (v.y - mu) * rstd * gv.y + bv.y;
    o.z = (v.z - mu) * rstd * gv.z + bv.z;
    o.w = (v.w - mu) * rstd * gv.w + bv.w;
    ((float4*)(out + (size_t)row * EE))[tid] = o;
    if (EMIT) {
        uint32_t h0, h1, l0, l1;
        split2(o.x, o.y, h0, l0);
        split2(o.z, o.w, h1, l1);
        ((uint2*)(oh + (size_t)row * EE))[tid] = make_uint2(h0, h1);
        ((uint2*)(ol + (size_t)row * EE))[tid] = make_uint2(l0, l1);
    }
}

// ---------------------------------------------------------------------------
// Launch
// ---------------------------------------------------------------------------
extern "C" void kernel_launch(void* const* d_in, const int* in_sizes, int n_in,
                              void* d_out, int out_size)
{
    (void)in_sizes; (void)n_in; (void)out_size;
    const float* x     = (const float*)d_in[0];
    const float* w_qkv = (const float*)d_in[1];
    const float* b_qkv = (const float*)d_in[2];
    const float* w_out = (const float*)d_in[3];
    const float* b_out = (const float*)d_in[4];
    const float* w1    = (const float*)d_in[5];
    const float* b1    = (const float*)d_in[6];
    const float* w2    = (const float*)d_in[7];
    const float* b2    = (const float*)d_in[8];
    const float* g1    = (const float*)d_in[9];
    const float* be1   = (const float*)d_in[10];
    const float* g2    = (const float*)d_in[11];
    const float* be2   = (const float*)d_in[12];
    float* out = (float*)d_out;

    float *p_qkv, *p_r1, *p_x1, *p_r2;
    bf16 *p_xh, *p_xl, *p_ath, *p_atl, *p_x1h, *p_x1l, *p_hh, *p_hl;
    bf16 *p_wqh, *p_wql, *p_woh, *p_wol, *p_w1h, *p_w1l, *p_w2h, *p_w2l;
    cudaGetSymbolAddress((void**)&p_qkv, g_qkv);
    cudaGetSymbolAddress((void**)&p_r1,  g_r1);
    cudaGetSymbolAddress((void**)&p_x1,  g_x1);
    cudaGetSymbolAddress((void**)&p_r2,  g_r2);
    cudaGetSymbolAddress((void**)&p_xh,  g_x_h);
    cudaGetSymbolAddress((void**)&p_xl,  g_x_l);
    cudaGetSymbolAddress((void**)&p_ath, g_att_h);
    cudaGetSymbolAddress((void**)&p_atl, g_att_l);
    cudaGetSymbolAddress((void**)&p_x1h, g_x1_h);
    cudaGetSymbolAddress((void**)&p_x1l, g_x1_l);
    cudaGetSymbolAddress((void**)&p_hh,  g_h_h);
    cudaGetSymbolAddress((void**)&p_hl,  g_h_l);
    cudaGetSymbolAddress((void**)&p_wqh, g_wqkv_h);
    cudaGetSymbolAddress((void**)&p_wql, g_wqkv_l);
    cudaGetSymbolAddress((void**)&p_woh, g_wout_h);
    cudaGetSymbolAddress((void**)&p_wol, g_wout_l);
    cudaGetSymbolAddress((void**)&p_w1h, g_w1_h);
    cudaGetSymbolAddress((void**)&p_w1l, g_w1_l);
    cudaGetSymbolAddress((void**)&p_w2h, g_w2_h);
    cudaGetSymbolAddress((void**)&p_w2l, g_w2_l);

    cudaFuncSetAttribute(attn_mma, cudaFuncAttributeMaxDynamicSharedMemorySize, ATT_SMEM);
    cudaFuncSetAttribute(gemm_bf<false, false, false>, cudaFuncAttributeMaxDynamicSharedMemorySize, GSM_TOTAL);
    cudaFuncSetAttribute(gemm_bf<false, true,  false>, cudaFuncAttributeMaxDynamicSharedMemorySize, GSM_TOTAL);
    cudaFuncSetAttribute(gemm_bf<true,  false, true>,  cudaFuncAttributeMaxDynamicSharedMemorySize, GSM_TOTAL);

    // 0) split inputs/weights to bf16 hi/lo
    split_kernel<<<(MR * EE / 4) / 256, 256>>>(x, p_xh, p_xl, MR * EE / 4);
    split_kernel<<<(3 * EE * EE / 4) / 256, 256>>>(w_qkv, p_wqh, p_wql, 3 * EE * EE / 4);
    split_kernel<<<(EE * EE / 4) / 256, 256>>>(w_out, p_woh, p_wol, EE * EE / 4);
    split_kernel<<<(FFD * EE / 4) / 256, 256>>>(w1, p_w1h, p_w1l, FFD * EE / 4);
    split_kernel<<<(EE * FFD / 4) / 256, 256>>>(w2, p_w2h, p_w2l, EE * FFD / 4);

    // 1) QKV projection -> fp32 qkv
    gemm_bf<false, false, false><<<dim3(3 * EE / 128, MR / 128), 256, GSM_TOTAL>>>(
        p_xh, p_xl, p_wqh, p_wql, b_qkv, nullptr, p_qkv, nullptr, nullptr, 3 * EE, EE);

    // 2) attention -> bf16 hi/lo
    attn_mma<<<dim3(SS / 128, BB * HHN), 256, ATT_SMEM>>>(p_qkv, p_ath, p_atl);

    // 3) out-proj + residual(x) -> r1 fp32
    gemm_bf<false, true, false><<<dim3(EE / 128, MR / 128), 256, GSM_TOTAL>>>(
        p_ath, p_atl, p_woh, p_wol, b_out, x, p_r1, nullptr, nullptr, EE, EE);

    // 4) LN1 -> x1 fp32 + bf16 hi/lo
    ln_kernel<true><<<MR, 256>>>(p_r1, g1, be1, p_x1, p_x1h, p_x1l);

    // 5) FFN up + ReLU -> h bf16 hi/lo
    gemm_bf<true, false, true><<<dim3(FFD / 128, MR / 128), 256, GSM_TOTAL>>>(
        p_x1h, p_x1l, p_w1h, p_w1l, b1, nullptr, nullptr, p_hh, p_hl, FFD, EE);

    // 6) FFN down + residual(x1) -> r2 fp32
    gemm_bf<false, true, false><<<dim3(EE / 128, MR / 128), 256, GSM_TOTAL>>>(
        p_hh, p_hl, p_w2h, p_w2l, b2, p_x1, p_r2, nullptr, nullptr, EE, FFD);

    // 7) LN2 -> out
    ln_kernel<false><<<MR, 256>>>(p_r2, g2, be2, out, nullptr, nullptr);
}